// round 2
// baseline (speedup 1.0000x reference)
#include <cuda_runtime.h>

#define NCELL   65536
#define TSTEPS  365
#define HID     64
#define G3      192
#define CPB     128   // cells (threads) per block

// ---------- packed f32x2 helpers (Blackwell FFMA2, PTX-only) ----------
__device__ __forceinline__ unsigned long long pk2(float a, float b) {
    unsigned long long r;
    asm("mov.b64 %0, {%1, %2};"
        : "=l"(r) : "r"(__float_as_uint(a)), "r"(__float_as_uint(b)));
    return r;
}
__device__ __forceinline__ void fma2(unsigned long long& d,
                                     unsigned long long a,
                                     unsigned long long b) {
    asm("fma.rn.f32x2 %0, %1, %2, %0;" : "+l"(d) : "l"(a), "l"(b));
}
__device__ __forceinline__ float2 up2(unsigned long long v) {
    unsigned lo, hi;
    asm("mov.b64 {%0, %1}, %2;" : "=r"(lo), "=r"(hi) : "l"(v));
    return make_float2(__uint_as_float(lo), __uint_as_float(hi));
}

__device__ __forceinline__ float sigm(float x) {
    return 1.0f / (1.0f + __expf(-x));
}

// ---------- 64x64 mat-vec slice for one gate (G = 0 / 64 / 128) ----------
// Wt is W_hh transposed: Wt[j*192 + k] = W_hh[k*64 + j]
// hcol points at this thread's hidden column: h_sh + tid, stride CPB
// acc[m] packs gate-local outputs (2m, 2m+1)
template <int G>
__device__ __forceinline__ void mv64(const float* __restrict__ Wt,
                                     const float* __restrict__ hcol,
                                     unsigned long long acc[32]) {
#pragma unroll
    for (int m = 0; m < 32; ++m) acc[m] = 0ull;
#pragma unroll 2
    for (int j = 0; j < HID; ++j) {
        float hj = hcol[j * CPB];
        unsigned long long h2 = pk2(hj, hj);
        const ulonglong2* w =
            reinterpret_cast<const ulonglong2*>(Wt + j * G3 + G);
#pragma unroll
        for (int q = 0; q < 16; ++q) {
            ulonglong2 wv = w[q];          // 4 consecutive k-weights (LDS.128, uniform -> broadcast)
            fma2(acc[2 * q + 0], wv.x, h2);
            fma2(acc[2 * q + 1], wv.y, h2);
        }
    }
}

// dynamic smem layout (floats):
//   Wt      [64*192] = 12288
//   h_sh    [64*CPB] =  8192
//   wih0    [192]
//   wih1    [192]
//   biasS   [192]
//   biasnS  [64]
//   outwS   [64]
#define SM_FLOATS (12288 + 8192 + 192 * 3 + 64 + 64)

__global__ void __launch_bounds__(CPB, 2)
gru_persistent_kernel(const float* __restrict__ precip,
                      const float* __restrict__ temp,
                      const float* __restrict__ w_ih,
                      const float* __restrict__ w_hh,
                      const float* __restrict__ bias,
                      const float* __restrict__ bias_n,
                      const float* __restrict__ out_w,
                      const float* __restrict__ out_b,
                      const float* __restrict__ init_h,
                      float* __restrict__ out) {
    extern __shared__ float sm[];
    float* Wt     = sm;                  // 12288
    float* h_sh   = Wt + 12288;          // 8192
    float* wih0   = h_sh + 8192;         // 192
    float* wih1   = wih0 + G3;           // 192
    float* biasS  = wih1 + G3;           // 192
    float* biasnS = biasS + G3;          // 64
    float* outwS  = biasnS + HID;        // 64

    const int tid  = threadIdx.x;
    const int cell = blockIdx.x * CPB + tid;

    // ---- stage weights into smem (transpose W_hh) ----
    for (int i = tid; i < G3 * HID; i += CPB) {
        int k = i / HID, j = i % HID;
        Wt[j * G3 + k] = w_hh[i];
    }
    for (int k = tid; k < G3; k += CPB) {
        wih0[k]  = w_ih[2 * k];
        wih1[k]  = w_ih[2 * k + 1];
        biasS[k] = bias[k];
    }
    if (tid < HID) {
        biasnS[tid] = bias_n[tid];
        outwS[tid]  = out_w[tid];
    }
    // init hidden state: same init_h broadcast to every cell
#pragma unroll 4
    for (int j = 0; j < HID; ++j) h_sh[j * CPB + tid] = init_h[j];
    __syncthreads();

    const float ob = out_b[0];
    const float* hcol = h_sh + tid;

    float R[HID];  // reset, then reused as "new"

    for (int t = 0; t < TSTEPS; ++t) {
        const int base = t * NCELL + cell;
        const float p  = precip[base];
        const float tm = temp[base];

        unsigned long long acc[32];

        // ---- pass 1: reset gate (k = 0..63) ----
        mv64<0>(Wt, hcol, acc);
#pragma unroll
        for (int m = 0; m < 32; ++m) {
            float2 hr = up2(acc[m]);
            int k0 = 2 * m, k1 = 2 * m + 1;
            float ig0 = fmaf(wih0[k0], p, fmaf(wih1[k0], tm, biasS[k0]));
            float ig1 = fmaf(wih0[k1], p, fmaf(wih1[k1], tm, biasS[k1]));
            R[k0] = sigm(ig0 + hr.x);
            R[k1] = sigm(ig1 + hr.y);
        }

        // ---- pass 2: candidate gate (k = 128..191): new = tanh(in + r*(hn + bn)) ----
        mv64<128>(Wt, hcol, acc);
#pragma unroll
        for (int m = 0; m < 32; ++m) {
            float2 hn = up2(acc[m]);
            int k0 = 2 * m, k1 = 2 * m + 1;
            float ig0 = fmaf(wih0[128 + k0], p, fmaf(wih1[128 + k0], tm, biasS[128 + k0]));
            float ig1 = fmaf(wih0[128 + k1], p, fmaf(wih1[128 + k1], tm, biasS[128 + k1]));
            R[k0] = tanhf(fmaf(R[k0], hn.x + biasnS[k0], ig0));
            R[k1] = tanhf(fmaf(R[k1], hn.y + biasnS[k1], ig1));
        }

        // ---- pass 3: update gate (k = 64..127) + state update + output ----
        mv64<64>(Wt, hcol, acc);
        float y = ob;
#pragma unroll
        for (int m = 0; m < 32; ++m) {
            float2 hz = up2(acc[m]);
            int k0 = 2 * m, k1 = 2 * m + 1;
            float ig0 = fmaf(wih0[64 + k0], p, fmaf(wih1[64 + k0], tm, biasS[64 + k0]));
            float ig1 = fmaf(wih0[64 + k1], p, fmaf(wih1[64 + k1], tm, biasS[64 + k1]));
            float u0 = sigm(ig0 + hz.x);
            float u1 = sigm(ig1 + hz.y);
            float hold0 = h_sh[k0 * CPB + tid];
            float hold1 = h_sh[k1 * CPB + tid];
            float hn0 = fmaf(u0, hold0 - R[k0], R[k0]);   // new + u*(h - new)
            float hn1 = fmaf(u1, hold1 - R[k1], R[k1]);
            h_sh[k0 * CPB + tid] = hn0;
            h_sh[k1 * CPB + tid] = hn1;
            y = fmaf(outwS[k0], hn0, y);
            y = fmaf(outwS[k1], hn1, y);
        }

        out[base] = y;   // smb[t, cell]
    }

    // ---- final hidden state: out[T*H*W + cell*64 + k] ----
    float* fo = out + (long long)TSTEPS * NCELL + (long long)cell * HID;
#pragma unroll 4
    for (int k = 0; k < HID; ++k) fo[k] = h_sh[k * CPB + tid];
}

extern "C" void kernel_launch(void* const* d_in, const int* in_sizes, int n_in,
                              void* d_out, int out_size) {
    const float* precip = (const float*)d_in[0];
    const float* temp   = (const float*)d_in[1];
    const float* w_ih   = (const float*)d_in[2];
    const float* w_hh   = (const float*)d_in[3];
    const float* bias   = (const float*)d_in[4];
    const float* bias_n = (const float*)d_in[5];
    const float* out_w  = (const float*)d_in[6];
    const float* out_b  = (const float*)d_in[7];
    const float* init_h = (const float*)d_in[8];
    float* out = (float*)d_out;

    const int smem_bytes = SM_FLOATS * sizeof(float);  // 84736 B
    cudaFuncSetAttribute(gru_persistent_kernel,
                         cudaFuncAttributeMaxDynamicSharedMemorySize,
                         smem_bytes);

    gru_persistent_kernel<<<NCELL / CPB, CPB, smem_bytes>>>(
        precip, temp, w_ih, w_hh, bias, bias_n, out_w, out_b, init_h, out);
}

// round 3
// speedup vs baseline: 1.2499x; 1.2499x over previous
#include <cuda_runtime.h>

#define NCELL   65536
#define TSTEPS  365
#define HID     64
#define G3      192
#define CELLS_PB 128
#define THREADS  256

// ---------- packed f32x2 helpers (Blackwell FFMA2, PTX-only) ----------
__device__ __forceinline__ unsigned long long pk2(float a, float b) {
    unsigned long long r;
    asm("mov.b64 %0, {%1, %2};"
        : "=l"(r) : "r"(__float_as_uint(a)), "r"(__float_as_uint(b)));
    return r;
}
__device__ __forceinline__ void fma2(unsigned long long& d,
                                     unsigned long long a,
                                     unsigned long long b) {
    asm("fma.rn.f32x2 %0, %1, %2, %0;" : "+l"(d) : "l"(a), "l"(b));
}
__device__ __forceinline__ float2 up2(unsigned long long v) {
    unsigned lo, hi;
    asm("mov.b64 {%0, %1}, %2;" : "=r"(lo), "=r"(hi) : "l"(v));
    return make_float2(__uint_as_float(lo), __uint_as_float(hi));
}
__device__ __forceinline__ float sigm(float x) {
    return 1.0f / (1.0f + __expf(-x));
}

// ---------- half mat-vec for one gate ----------
// Wt[j*192 + k] = W_hh[k*64 + j]  (transposed, gate-contiguous in k)
// This thread covers k = 8*i + 4*slice + {0..3}, i = 0..7  (32 outputs)
// acc[2i]   packs (8i+4s+0, 8i+4s+1), acc[2i+1] packs (+2,+3)
template <int G>
__device__ __forceinline__ void mv_half(const float* __restrict__ Wt,
                                        const float* __restrict__ hcol,
                                        int slice,
                                        unsigned long long acc[16]) {
#pragma unroll
    for (int m = 0; m < 16; ++m) acc[m] = 0ull;
#pragma unroll 4
    for (int j = 0; j < HID; ++j) {
        float hj = hcol[j * CELLS_PB];
        unsigned long long h2 = pk2(hj, hj);
        const ulonglong2* w =
            reinterpret_cast<const ulonglong2*>(Wt + j * G3 + G) + slice;
#pragma unroll
        for (int i = 0; i < 8; ++i) {
            ulonglong2 wv = w[2 * i];       // 4 consecutive k-weights (LDS.128)
            fma2(acc[2 * i + 0], wv.x, h2);
            fma2(acc[2 * i + 1], wv.y, h2);
        }
    }
}

// dynamic smem (floats):
//   Wt   [64*192] = 12288
//   h_sh [64*128] =  8192   layout [k][cell]
//   wpk  [192*4]  =   768   per-k float4: (wih0, wih1, bias, extra)
//                           extra = out_w[k-64]  for k in [64,128)
//                                 = bias_n[k-128] for k in [128,192)
#define SM_FLOATS (12288 + 8192 + 768)

__global__ void __launch_bounds__(THREADS, 2)
gru_persistent_kernel(const float* __restrict__ precip,
                      const float* __restrict__ temp,
                      const float* __restrict__ w_ih,
                      const float* __restrict__ w_hh,
                      const float* __restrict__ bias,
                      const float* __restrict__ bias_n,
                      const float* __restrict__ out_w,
                      const float* __restrict__ out_b,
                      const float* __restrict__ init_h,
                      float* __restrict__ out) {
    extern __shared__ float sm[];
    float*  Wt   = sm;                 // 12288
    float*  h_sh = Wt + 12288;         // 8192
    float4* wpk  = reinterpret_cast<float4*>(h_sh + 8192);  // 192 float4

    const int tid   = threadIdx.x;
    const int ci    = tid >> 1;        // cell index in block (0..127)
    const int slice = tid & 1;         // which half of the outputs
    const int cell  = blockIdx.x * CELLS_PB + ci;

    // ---- stage weights (transpose W_hh) ----
    for (int i = tid; i < G3 * HID; i += THREADS) {
        int k = i >> 6, j = i & 63;
        Wt[j * G3 + k] = w_hh[i];
    }
    for (int k = tid; k < G3; k += THREADS) {
        float ex = 0.0f;
        if (k >= 128)      ex = bias_n[k - 128];
        else if (k >= 64)  ex = out_w[k - 64];
        wpk[k] = make_float4(w_ih[2 * k], w_ih[2 * k + 1], bias[k], ex);
    }
    for (int i = tid; i < HID * CELLS_PB; i += THREADS)
        h_sh[i] = init_h[i >> 7];      // broadcast init_h[j] to all cells
    __syncthreads();

    const float ob = out_b[0];
    const float* hcol = h_sh + ci;

    float R[32];                       // reset, then reused as "new"
    unsigned long long acc[16];

    for (int t = 0; t < TSTEPS; ++t) {
        const int base = t * NCELL + cell;
        const float p  = precip[base];
        const float tm = temp[base];

        // ---- pass 1: reset gate ----
        mv_half<0>(Wt, hcol, slice, acc);
#pragma unroll
        for (int m = 0; m < 16; ++m) {
            float2 hr = up2(acc[m]);
            int kb = 8 * (m >> 1) + 4 * slice + 2 * (m & 1);
            float4 c0 = wpk[kb], c1 = wpk[kb + 1];
            float ig0 = fmaf(c0.x, p, fmaf(c0.y, tm, c0.z));
            float ig1 = fmaf(c1.x, p, fmaf(c1.y, tm, c1.z));
            R[2 * m + 0] = sigm(ig0 + hr.x);
            R[2 * m + 1] = sigm(ig1 + hr.y);
        }

        // ---- pass 2: candidate: new = tanh(in + r*(hn + bias_n)) ----
        mv_half<128>(Wt, hcol, slice, acc);
#pragma unroll
        for (int m = 0; m < 16; ++m) {
            float2 hn = up2(acc[m]);
            int kb = 8 * (m >> 1) + 4 * slice + 2 * (m & 1);
            float4 c0 = wpk[128 + kb], c1 = wpk[128 + kb + 1];
            float ig0 = fmaf(c0.x, p, fmaf(c0.y, tm, c0.z));
            float ig1 = fmaf(c1.x, p, fmaf(c1.y, tm, c1.z));
            R[2 * m + 0] = tanhf(fmaf(R[2 * m + 0], hn.x + c0.w, ig0));
            R[2 * m + 1] = tanhf(fmaf(R[2 * m + 1], hn.y + c1.w, ig1));
        }

        // ---- pass 3: update gate + state update + output ----
        mv_half<64>(Wt, hcol, slice, acc);
        float y = (slice == 0) ? ob : 0.0f;
#pragma unroll
        for (int m = 0; m < 16; ++m) {
            float2 hz = up2(acc[m]);
            int kb = 8 * (m >> 1) + 4 * slice + 2 * (m & 1);
            float4 c0 = wpk[64 + kb], c1 = wpk[64 + kb + 1];
            float ig0 = fmaf(c0.x, p, fmaf(c0.y, tm, c0.z));
            float ig1 = fmaf(c1.x, p, fmaf(c1.y, tm, c1.z));
            float u0 = sigm(ig0 + hz.x);
            float u1 = sigm(ig1 + hz.y);
            float hold0 = h_sh[kb * CELLS_PB + ci];
            float hold1 = h_sh[(kb + 1) * CELLS_PB + ci];
            float n0 = R[2 * m + 0], n1 = R[2 * m + 1];
            float hn0 = fmaf(u0, hold0 - n0, n0);   // new + u*(h - new)
            float hn1 = fmaf(u1, hold1 - n1, n1);
            h_sh[kb * CELLS_PB + ci]       = hn0;
            h_sh[(kb + 1) * CELLS_PB + ci] = hn1;
            y = fmaf(c0.w, hn0, y);                 // c0.w = out_w[kb]
            y = fmaf(c1.w, hn1, y);
        }

        // combine the two slices' partial dot products
        y += __shfl_xor_sync(0xFFFFFFFFu, y, 1);
        if (slice == 0) out[base] = y;              // smb[t, cell]

        __syncwarp();   // pair lane's h writes visible before next step's reads
    }

    // ---- final hidden state: out[T*N + cell*64 + k] for this thread's ks ----
    float* fo = out + (long long)TSTEPS * NCELL + (long long)cell * HID;
#pragma unroll
    for (int l = 0; l < 32; ++l) {
        int k = 8 * (l >> 2) + 4 * slice + (l & 3);
        fo[k] = h_sh[k * CELLS_PB + ci];
    }
}

extern "C" void kernel_launch(void* const* d_in, const int* in_sizes, int n_in,
                              void* d_out, int out_size) {
    const float* precip = (const float*)d_in[0];
    const float* temp   = (const float*)d_in[1];
    const float* w_ih   = (const float*)d_in[2];
    const float* w_hh   = (const float*)d_in[3];
    const float* bias   = (const float*)d_in[4];
    const float* bias_n = (const float*)d_in[5];
    const float* out_w  = (const float*)d_in[6];
    const float* out_b  = (const float*)d_in[7];
    const float* init_h = (const float*)d_in[8];
    float* out = (float*)d_out;

    const int smem_bytes = SM_FLOATS * sizeof(float);  // 84992 B
    cudaFuncSetAttribute(gru_persistent_kernel,
                         cudaFuncAttributeMaxDynamicSharedMemorySize,
                         smem_bytes);

    gru_persistent_kernel<<<NCELL / CELLS_PB, THREADS, smem_bytes>>>(
        precip, temp, w_ih, w_hh, bias, bias_n, out_w, out_b, init_h, out);
}